// round 1
// baseline (speedup 1.0000x reference)
#include <cuda_runtime.h>

#define T_TOK 2048
#define H_DIM 2048
#define I_DIM 5632
#define N_EXP 8
#define RMAX  4608
#define MAXT  72

// Scratch (static __device__ globals: allocation-free per harness rules)
__device__ float d_Xg [RMAX * H_DIM];   // gathered token rows per expert segment
__device__ float d_act[RMAX * I_DIM];   // silu(g)*u
__device__ float d_ys [RMAX * H_DIM];   // weighted down-proj per (token,slot) row
__device__ int   d_topi[T_TOK * 2];
__device__ float d_topw[T_TOK * 2];
__device__ int   d_cnt [N_EXP];
__device__ int   d_fill[N_EXP];
__device__ int   d_off [N_EXP];
__device__ int   d_tile_expert[MAXT];
__device__ int   d_ntiles;
__device__ int   d_nrows;
__device__ float d_row_w[RMAX];
__device__ int   d_row_of[T_TOK * 2];

typedef unsigned long long ull;

__device__ __forceinline__ ull pk2(float lo, float hi) {
    ull r; asm("mov.b64 %0,{%1,%2};" : "=l"(r) : "f"(lo), "f"(hi)); return r;
}
__device__ __forceinline__ void fma2(ull& d, ull a, ull b) {
    asm("fma.rn.f32x2 %0,%1,%2,%0;" : "+l"(d) : "l"(a), "l"(b));
}
__device__ __forceinline__ float2 up2(ull v) {
    float2 r; asm("mov.b64 {%0,%1},%2;" : "=f"(r.x), "=f"(r.y) : "l"(v)); return r;
}

// ---------------------------------------------------------------------------
__global__ void k_init() {
    int i = threadIdx.x;
    if (i < N_EXP) { d_cnt[i] = 0; d_fill[i] = 0; }
}

// One warp per token: 8 logits, softmax fp32, top-2, renormalize.
__global__ void k_router(const float* __restrict__ x, const float* __restrict__ gw) {
    int warp = threadIdx.x >> 5, lane = threadIdx.x & 31;
    int t = blockIdx.x * 8 + warp;
    const float* xr = x + (size_t)t * H_DIM;

    float acc[N_EXP];
#pragma unroll
    for (int e = 0; e < N_EXP; e++) acc[e] = 0.f;

    for (int h = lane; h < H_DIM; h += 32) {
        float xv = xr[h];
#pragma unroll
        for (int e = 0; e < N_EXP; e++) acc[e] += xv * gw[e * H_DIM + h];
    }
#pragma unroll
    for (int e = 0; e < N_EXP; e++) {
#pragma unroll
        for (int o = 16; o > 0; o >>= 1)
            acc[e] += __shfl_xor_sync(0xffffffffu, acc[e], o);
    }

    if (lane == 0) {
        float mx = acc[0];
#pragma unroll
        for (int e = 1; e < N_EXP; e++) mx = fmaxf(mx, acc[e]);
        float p[N_EXP], s = 0.f;
#pragma unroll
        for (int e = 0; e < N_EXP; e++) { p[e] = __expf(acc[e] - mx); s += p[e]; }
        float inv = 1.f / s;
#pragma unroll
        for (int e = 0; e < N_EXP; e++) p[e] *= inv;

        int i0 = 0;
#pragma unroll
        for (int e = 1; e < N_EXP; e++) if (p[e] > p[i0]) i0 = e;
        int i1 = (i0 == 0) ? 1 : 0;
#pragma unroll
        for (int e = 0; e < N_EXP; e++) if (e != i0 && p[e] > p[i1]) i1 = e;

        float sw = p[i0] + p[i1];
        d_topi[2 * t]     = i0; d_topw[2 * t]     = p[i0] / sw;
        d_topi[2 * t + 1] = i1; d_topw[2 * t + 1] = p[i1] / sw;
        atomicAdd(&d_cnt[i0], 1);
        atomicAdd(&d_cnt[i1], 1);
    }
}

// Padded (64-row) per-expert segment offsets + tile->expert map.
__global__ void k_offsets() {
    if (threadIdx.x == 0) {
        int acc = 0;
        for (int e = 0; e < N_EXP; e++) {
            d_off[e] = acc;
            int nt = (d_cnt[e] + 63) >> 6;
            int tb = acc >> 6;
            for (int j = 0; j < nt; j++) d_tile_expert[tb + j] = e;
            acc += nt << 6;
        }
        d_nrows  = acc;
        d_ntiles = acc >> 6;
    }
}

// One block per (token, slot): claim a row in the expert segment, copy x row.
__global__ void k_gather(const float* __restrict__ x) {
    int idx = blockIdx.x;
    int t = idx >> 1;
    __shared__ int rs;
    if (threadIdx.x == 0) {
        int e = d_topi[idx];
        int pos = atomicAdd(&d_fill[e], 1);
        int row = d_off[e] + pos;
        d_row_w[row] = d_topw[idx];
        d_row_of[idx] = row;
        rs = row;
    }
    __syncthreads();
    int row = rs;
    const float4* src = (const float4*)(x + (size_t)t * H_DIM);
    float4* dst = (float4*)(d_Xg + (size_t)row * H_DIM);
    for (int i = threadIdx.x; i < H_DIM / 4; i += blockDim.x) dst[i] = src[i];
}

// ---------------------------------------------------------------------------
// GEMM1: act[r, i] = silu(Xg[r,:]·Wg_e[i,:]) * (Xg[r,:]·Wu_e[i,:])
// 64x64 tile, BK=16, 256 threads, 4x4 per thread per matrix, packed f32x2 FMA.
__global__ void __launch_bounds__(256, 2)
k_gemm1(const float* __restrict__ wg, const float* __restrict__ wu) {
    if ((int)blockIdx.y >= d_ntiles) return;
    const int mt = blockIdx.y;
    const int e  = d_tile_expert[mt];
    const int r0 = mt * 64;
    const int i0 = blockIdx.x * 64;

    const int tid = threadIdx.x;
    const int lr = tid >> 2;           // 0..63: tile row loaded by this thread
    const int lc = (tid & 3) * 4;      // 0..12: k offset within chunk
    const int tx = tid & 15, ty = tid >> 4;

    __shared__ float As [16][64];
    __shared__ float Bgs[16][64];
    __shared__ float Bus[16][64];

    const float* A  = d_Xg + (size_t)(r0 + lr) * H_DIM + lc;
    const float* Bg = wg + ((size_t)e * I_DIM + i0 + lr) * H_DIM + lc;
    const float* Bu = wu + ((size_t)e * I_DIM + i0 + lr) * H_DIM + lc;

    ull ag[4][2], au[4][2];
#pragma unroll
    for (int j = 0; j < 4; j++) { ag[j][0] = 0ull; ag[j][1] = 0ull; au[j][0] = 0ull; au[j][1] = 0ull; }

    float4 ra = *(const float4*)A;
    float4 rg = *(const float4*)Bg;
    float4 ru = *(const float4*)Bu;

    for (int k0 = 0; k0 < H_DIM; k0 += 16) {
        As [lc + 0][lr] = ra.x; As [lc + 1][lr] = ra.y; As [lc + 2][lr] = ra.z; As [lc + 3][lr] = ra.w;
        Bgs[lc + 0][lr] = rg.x; Bgs[lc + 1][lr] = rg.y; Bgs[lc + 2][lr] = rg.z; Bgs[lc + 3][lr] = rg.w;
        Bus[lc + 0][lr] = ru.x; Bus[lc + 1][lr] = ru.y; Bus[lc + 2][lr] = ru.z; Bus[lc + 3][lr] = ru.w;
        __syncthreads();

        int kn = k0 + 16;
        if (kn < H_DIM) {
            ra = *(const float4*)(A + kn);
            rg = *(const float4*)(Bg + kn);
            ru = *(const float4*)(Bu + kn);
        }

#pragma unroll
        for (int kk = 0; kk < 16; kk++) {
            float4 a  = *(const float4*)&As [kk][ty * 4];
            float4 bg = *(const float4*)&Bgs[kk][tx * 4];
            float4 bu = *(const float4*)&Bus[kk][tx * 4];
            ull g01 = pk2(bg.x, bg.y), g23 = pk2(bg.z, bg.w);
            ull u01 = pk2(bu.x, bu.y), u23 = pk2(bu.z, bu.w);
            ull a0 = pk2(a.x, a.x), a1 = pk2(a.y, a.y), a2 = pk2(a.z, a.z), a3 = pk2(a.w, a.w);
            fma2(ag[0][0], a0, g01); fma2(ag[0][1], a0, g23);
            fma2(au[0][0], a0, u01); fma2(au[0][1], a0, u23);
            fma2(ag[1][0], a1, g01); fma2(ag[1][1], a1, g23);
            fma2(au[1][0], a1, u01); fma2(au[1][1], a1, u23);
            fma2(ag[2][0], a2, g01); fma2(ag[2][1], a2, g23);
            fma2(au[2][0], a2, u01); fma2(au[2][1], a2, u23);
            fma2(ag[3][0], a3, g01); fma2(ag[3][1], a3, g23);
            fma2(au[3][0], a3, u01); fma2(au[3][1], a3, u23);
        }
        __syncthreads();
    }

#pragma unroll
    for (int j = 0; j < 4; j++) {
        float2 gA = up2(ag[j][0]), gB = up2(ag[j][1]);
        float2 uA = up2(au[j][0]), uB = up2(au[j][1]);
        float4 o;
        o.x = gA.x / (1.f + __expf(-gA.x)) * uA.x;
        o.y = gA.y / (1.f + __expf(-gA.y)) * uA.y;
        o.z = gB.x / (1.f + __expf(-gB.x)) * uB.x;
        o.w = gB.y / (1.f + __expf(-gB.y)) * uB.y;
        *(float4*)(d_act + (size_t)(r0 + ty * 4 + j) * I_DIM + i0 + tx * 4) = o;
    }
}

// ---------------------------------------------------------------------------
// GEMM2: ys[r, h] = w_r * (act[r,:]·Wd_e[h,:]),  K = I_DIM
__global__ void __launch_bounds__(256, 2)
k_gemm2(const float* __restrict__ wd) {
    if ((int)blockIdx.y >= d_ntiles) return;
    const int mt = blockIdx.y;
    const int e  = d_tile_expert[mt];
    const int r0 = mt * 64;
    const int h0 = blockIdx.x * 64;

    const int tid = threadIdx.x;
    const int lr = tid >> 2;
    const int lc = (tid & 3) * 4;
    const int tx = tid & 15, ty = tid >> 4;

    __shared__ float As[16][64];
    __shared__ float Bs[16][64];

    const float* A = d_act + (size_t)(r0 + lr) * I_DIM + lc;
    const float* B = wd + ((size_t)e * H_DIM + h0 + lr) * I_DIM + lc;

    ull ac[4][2];
#pragma unroll
    for (int j = 0; j < 4; j++) { ac[j][0] = 0ull; ac[j][1] = 0ull; }

    float4 ra = *(const float4*)A;
    float4 rb = *(const float4*)B;

    for (int k0 = 0; k0 < I_DIM; k0 += 16) {
        As[lc + 0][lr] = ra.x; As[lc + 1][lr] = ra.y; As[lc + 2][lr] = ra.z; As[lc + 3][lr] = ra.w;
        Bs[lc + 0][lr] = rb.x; Bs[lc + 1][lr] = rb.y; Bs[lc + 2][lr] = rb.z; Bs[lc + 3][lr] = rb.w;
        __syncthreads();

        int kn = k0 + 16;
        if (kn < I_DIM) {
            ra = *(const float4*)(A + kn);
            rb = *(const float4*)(B + kn);
        }

#pragma unroll
        for (int kk = 0; kk < 16; kk++) {
            float4 a = *(const float4*)&As[kk][ty * 4];
            float4 b = *(const float4*)&Bs[kk][tx * 4];
            ull b01 = pk2(b.x, b.y), b23 = pk2(b.z, b.w);
            ull a0 = pk2(a.x, a.x), a1 = pk2(a.y, a.y), a2 = pk2(a.z, a.z), a3 = pk2(a.w, a.w);
            fma2(ac[0][0], a0, b01); fma2(ac[0][1], a0, b23);
            fma2(ac[1][0], a1, b01); fma2(ac[1][1], a1, b23);
            fma2(ac[2][0], a2, b01); fma2(ac[2][1], a2, b23);
            fma2(ac[3][0], a3, b01); fma2(ac[3][1], a3, b23);
        }
        __syncthreads();
    }

#pragma unroll
    for (int j = 0; j < 4; j++) {
        float w = d_row_w[r0 + ty * 4 + j];
        float2 yA = up2(ac[j][0]), yB = up2(ac[j][1]);
        float4 o;
        o.x = yA.x * w; o.y = yA.y * w; o.z = yB.x * w; o.w = yB.y * w;
        *(float4*)(d_ys + (size_t)(r0 + ty * 4 + j) * H_DIM + h0 + tx * 4) = o;
    }
}

// out[t] = ys[row(t,0)] + ys[row(t,1)]  (weights already applied; deterministic)
__global__ void k_combine(float* __restrict__ out) {
    int t = blockIdx.x;
    int ra = d_row_of[2 * t];
    int rb = d_row_of[2 * t + 1];
    const float4* pa = (const float4*)(d_ys + (size_t)ra * H_DIM);
    const float4* pb = (const float4*)(d_ys + (size_t)rb * H_DIM);
    float4* po = (float4*)(out + (size_t)t * H_DIM);
    for (int i = threadIdx.x; i < H_DIM / 4; i += blockDim.x) {
        float4 a = pa[i], b = pb[i];
        float4 o; o.x = a.x + b.x; o.y = a.y + b.y; o.z = a.z + b.z; o.w = a.w + b.w;
        po[i] = o;
    }
}

// ---------------------------------------------------------------------------
extern "C" void kernel_launch(void* const* d_in, const int* in_sizes, int n_in,
                              void* d_out, int out_size) {
    const float* x  = (const float*)d_in[0];   // hidden_states [1,2048,2048]
    const float* gw = (const float*)d_in[1];   // gate_w [8,2048]
    const float* wg = (const float*)d_in[2];   // w_gate [8,5632,2048]
    const float* wu = (const float*)d_in[3];   // w_up   [8,5632,2048]
    const float* wd = (const float*)d_in[4];   // w_down [8,2048,5632]
    float* out = (float*)d_out;                // [1,2048,2048]

    k_init<<<1, 32>>>();
    k_router<<<T_TOK / 8, 256>>>(x, gw);
    k_offsets<<<1, 1>>>();
    k_gather<<<T_TOK * 2, 256>>>(x);

    dim3 g1(I_DIM / 64, MAXT);
    k_gemm1<<<g1, 256>>>(wg, wu);

    dim3 g2(H_DIM / 64, MAXT);
    k_gemm2<<<g2, 256>>>(wd);

    k_combine<<<T_TOK, 256>>>(out);
}

// round 2
// speedup vs baseline: 1.0018x; 1.0018x over previous
#include <cuda_runtime.h>

#define T_TOK 2048
#define H_DIM 2048
#define I_DIM 5632
#define N_EXP 8
#define RMAX  4608
#define MAXT  72

// Scratch (static __device__ globals: allocation-free per harness rules)
__device__ float d_Xg [RMAX * H_DIM];   // gathered token rows per expert segment
__device__ float d_act[RMAX * I_DIM];   // silu(g)*u
__device__ float d_ys [RMAX * H_DIM];   // weighted down-proj per (token,slot) row
__device__ int   d_topi[T_TOK * 2];
__device__ float d_topw[T_TOK * 2];
__device__ int   d_cnt [N_EXP];
__device__ int   d_fill[N_EXP];
__device__ int   d_off [N_EXP];
__device__ int   d_tile_expert[MAXT];
__device__ int   d_ntiles;
__device__ int   d_nrows;
__device__ float d_row_w[RMAX];
__device__ int   d_row_of[T_TOK * 2];

typedef unsigned long long ull;

__device__ __forceinline__ ull pk2(float lo, float hi) {
    ull r; asm("mov.b64 %0,{%1,%2};" : "=l"(r) : "f"(lo), "f"(hi)); return r;
}
__device__ __forceinline__ void fma2(ull& d, ull a, ull b) {
    asm("fma.rn.f32x2 %0,%1,%2,%0;" : "+l"(d) : "l"(a), "l"(b));
}
__device__ __forceinline__ float2 up2(ull v) {
    float2 r; asm("mov.b64 {%0,%1},%2;" : "=f"(r.x), "=f"(r.y) : "l"(v)); return r;
}

// ---------------------------------------------------------------------------
__global__ void k_init() {
    int i = threadIdx.x;
    if (i < N_EXP) { d_cnt[i] = 0; d_fill[i] = 0; }
}

// One warp per token: 8 logits, softmax fp32, top-2, renormalize.
__global__ void k_router(const float* __restrict__ x, const float* __restrict__ gw) {
    int warp = threadIdx.x >> 5, lane = threadIdx.x & 31;
    int t = blockIdx.x * 8 + warp;
    const float* xr = x + (size_t)t * H_DIM;

    float acc[N_EXP];
#pragma unroll
    for (int e = 0; e < N_EXP; e++) acc[e] = 0.f;

    for (int h = lane; h < H_DIM; h += 32) {
        float xv = xr[h];
#pragma unroll
        for (int e = 0; e < N_EXP; e++) acc[e] += xv * gw[e * H_DIM + h];
    }
#pragma unroll
    for (int e = 0; e < N_EXP; e++) {
#pragma unroll
        for (int o = 16; o > 0; o >>= 1)
            acc[e] += __shfl_xor_sync(0xffffffffu, acc[e], o);
    }

    if (lane == 0) {
        float mx = acc[0];
#pragma unroll
        for (int e = 1; e < N_EXP; e++) mx = fmaxf(mx, acc[e]);
        float p[N_EXP], s = 0.f;
#pragma unroll
        for (int e = 0; e < N_EXP; e++) { p[e] = __expf(acc[e] - mx); s += p[e]; }
        float inv = 1.f / s;
#pragma unroll
        for (int e = 0; e < N_EXP; e++) p[e] *= inv;

        int i0 = 0;
#pragma unroll
        for (int e = 1; e < N_EXP; e++) if (p[e] > p[i0]) i0 = e;
        int i1 = (i0 == 0) ? 1 : 0;
#pragma unroll
        for (int e = 0; e < N_EXP; e++) if (e != i0 && p[e] > p[i1]) i1 = e;

        float sw = p[i0] + p[i1];
        d_topi[2 * t]     = i0; d_topw[2 * t]     = p[i0] / sw;
        d_topi[2 * t + 1] = i1; d_topw[2 * t + 1] = p[i1] / sw;
        atomicAdd(&d_cnt[i0], 1);
        atomicAdd(&d_cnt[i1], 1);
    }
}

// Padded (64-row) per-expert segment offsets + tile->expert map.
__global__ void k_offsets() {
    if (threadIdx.x == 0) {
        int acc = 0;
        for (int e = 0; e < N_EXP; e++) {
            d_off[e] = acc;
            int nt = (d_cnt[e] + 63) >> 6;
            int tb = acc >> 6;
            for (int j = 0; j < nt; j++) d_tile_expert[tb + j] = e;
            acc += nt << 6;
        }
        d_nrows  = acc;
        d_ntiles = acc >> 6;
    }
}

// One block per (token, slot): claim a row in the expert segment, copy x row.
__global__ void k_gather(const float* __restrict__ x) {
    int idx = blockIdx.x;
    int t = idx >> 1;
    __shared__ int rs;
    if (threadIdx.x == 0) {
        int e = d_topi[idx];
        int pos = atomicAdd(&d_fill[e], 1);
        int row = d_off[e] + pos;
        d_row_w[row] = d_topw[idx];
        d_row_of[idx] = row;
        rs = row;
    }
    __syncthreads();
    int row = rs;
    const float4* src = (const float4*)(x + (size_t)t * H_DIM);
    float4* dst = (float4*)(d_Xg + (size_t)row * H_DIM);
    for (int i = threadIdx.x; i < H_DIM / 4; i += blockDim.x) dst[i] = src[i];
}

// ---------------------------------------------------------------------------
// GEMM1: act[r, i] = silu(Xg[r,:]·Wg_e[i,:]) * (Xg[r,:]·Wu_e[i,:])
// 64x64 tile, BK=16, 256 threads, 4x4 per thread per matrix, packed f32x2 FMA.
__global__ void __launch_bounds__(256, 2)
k_gemm1(const float* __restrict__ wg, const float* __restrict__ wu) {
    if ((int)blockIdx.y >= d_ntiles) return;
    const int mt = blockIdx.y;
    const int e  = d_tile_expert[mt];
    const int r0 = mt * 64;
    const int i0 = blockIdx.x * 64;

    const int tid = threadIdx.x;
    const int lr = tid >> 2;           // 0..63: tile row loaded by this thread
    const int lc = (tid & 3) * 4;      // 0..12: k offset within chunk
    const int tx = tid & 15, ty = tid >> 4;

    __shared__ float As [16][64];
    __shared__ float Bgs[16][64];
    __shared__ float Bus[16][64];

    const float* A  = d_Xg + (size_t)(r0 + lr) * H_DIM + lc;
    const float* Bg = wg + ((size_t)e * I_DIM + i0 + lr) * H_DIM + lc;
    const float* Bu = wu + ((size_t)e * I_DIM + i0 + lr) * H_DIM + lc;

    ull ag[4][2], au[4][2];
#pragma unroll
    for (int j = 0; j < 4; j++) { ag[j][0] = 0ull; ag[j][1] = 0ull; au[j][0] = 0ull; au[j][1] = 0ull; }

    float4 ra = *(const float4*)A;
    float4 rg = *(const float4*)Bg;
    float4 ru = *(const float4*)Bu;

    for (int k0 = 0; k0 < H_DIM; k0 += 16) {
        As [lc + 0][lr] = ra.x; As [lc + 1][lr] = ra.y; As [lc + 2][lr] = ra.z; As [lc + 3][lr] = ra.w;
        Bgs[lc + 0][lr] = rg.x; Bgs[lc + 1][lr] = rg.y; Bgs[lc + 2][lr] = rg.z; Bgs[lc + 3][lr] = rg.w;
        Bus[lc + 0][lr] = ru.x; Bus[lc + 1][lr] = ru.y; Bus[lc + 2][lr] = ru.z; Bus[lc + 3][lr] = ru.w;
        __syncthreads();

        int kn = k0 + 16;
        if (kn < H_DIM) {
            ra = *(const float4*)(A + kn);
            rg = *(const float4*)(Bg + kn);
            ru = *(const float4*)(Bu + kn);
        }

#pragma unroll
        for (int kk = 0; kk < 16; kk++) {
            float4 a  = *(const float4*)&As [kk][ty * 4];
            float4 bg = *(const float4*)&Bgs[kk][tx * 4];
            float4 bu = *(const float4*)&Bus[kk][tx * 4];
            ull g01 = pk2(bg.x, bg.y), g23 = pk2(bg.z, bg.w);
            ull u01 = pk2(bu.x, bu.y), u23 = pk2(bu.z, bu.w);
            ull a0 = pk2(a.x, a.x), a1 = pk2(a.y, a.y), a2 = pk2(a.z, a.z), a3 = pk2(a.w, a.w);
            fma2(ag[0][0], a0, g01); fma2(ag[0][1], a0, g23);
            fma2(au[0][0], a0, u01); fma2(au[0][1], a0, u23);
            fma2(ag[1][0], a1, g01); fma2(ag[1][1], a1, g23);
            fma2(au[1][0], a1, u01); fma2(au[1][1], a1, u23);
            fma2(ag[2][0], a2, g01); fma2(ag[2][1], a2, g23);
            fma2(au[2][0], a2, u01); fma2(au[2][1], a2, u23);
            fma2(ag[3][0], a3, g01); fma2(ag[3][1], a3, g23);
            fma2(au[3][0], a3, u01); fma2(au[3][1], a3, u23);
        }
        __syncthreads();
    }

#pragma unroll
    for (int j = 0; j < 4; j++) {
        float2 gA = up2(ag[j][0]), gB = up2(ag[j][1]);
        float2 uA = up2(au[j][0]), uB = up2(au[j][1]);
        float4 o;
        o.x = gA.x / (1.f + __expf(-gA.x)) * uA.x;
        o.y = gA.y / (1.f + __expf(-gA.y)) * uA.y;
        o.z = gB.x / (1.f + __expf(-gB.x)) * uB.x;
        o.w = gB.y / (1.f + __expf(-gB.y)) * uB.y;
        *(float4*)(d_act + (size_t)(r0 + ty * 4 + j) * I_DIM + i0 + tx * 4) = o;
    }
}

// ---------------------------------------------------------------------------
// GEMM2: ys[r, h] = w_r * (act[r,:]·Wd_e[h,:]),  K = I_DIM
__global__ void __launch_bounds__(256, 2)
k_gemm2(const float* __restrict__ wd) {
    if ((int)blockIdx.y >= d_ntiles) return;
    const int mt = blockIdx.y;
    const int e  = d_tile_expert[mt];
    const int r0 = mt * 64;
    const int h0 = blockIdx.x * 64;

    const int tid = threadIdx.x;
    const int lr = tid >> 2;
    const int lc = (tid & 3) * 4;
    const int tx = tid & 15, ty = tid >> 4;

    __shared__ float As[16][64];
    __shared__ float Bs[16][64];

    const float* A = d_act + (size_t)(r0 + lr) * I_DIM + lc;
    const float* B = wd + ((size_t)e * H_DIM + h0 + lr) * I_DIM + lc;

    ull ac[4][2];
#pragma unroll
    for (int j = 0; j < 4; j++) { ac[j][0] = 0ull; ac[j][1] = 0ull; }

    float4 ra = *(const float4*)A;
    float4 rb = *(const float4*)B;

    for (int k0 = 0; k0 < I_DIM; k0 += 16) {
        As[lc + 0][lr] = ra.x; As[lc + 1][lr] = ra.y; As[lc + 2][lr] = ra.z; As[lc + 3][lr] = ra.w;
        Bs[lc + 0][lr] = rb.x; Bs[lc + 1][lr] = rb.y; Bs[lc + 2][lr] = rb.z; Bs[lc + 3][lr] = rb.w;
        __syncthreads();

        int kn = k0 + 16;
        if (kn < I_DIM) {
            ra = *(const float4*)(A + kn);
            rb = *(const float4*)(B + kn);
        }

#pragma unroll
        for (int kk = 0; kk < 16; kk++) {
            float4 a = *(const float4*)&As[kk][ty * 4];
            float4 b = *(const float4*)&Bs[kk][tx * 4];
            ull b01 = pk2(b.x, b.y), b23 = pk2(b.z, b.w);
            ull a0 = pk2(a.x, a.x), a1 = pk2(a.y, a.y), a2 = pk2(a.z, a.z), a3 = pk2(a.w, a.w);
            fma2(ac[0][0], a0, b01); fma2(ac[0][1], a0, b23);
            fma2(ac[1][0], a1, b01); fma2(ac[1][1], a1, b23);
            fma2(ac[2][0], a2, b01); fma2(ac[2][1], a2, b23);
            fma2(ac[3][0], a3, b01); fma2(ac[3][1], a3, b23);
        }
        __syncthreads();
    }

#pragma unroll
    for (int j = 0; j < 4; j++) {
        float w = d_row_w[r0 + ty * 4 + j];
        float2 yA = up2(ac[j][0]), yB = up2(ac[j][1]);
        float4 o;
        o.x = yA.x * w; o.y = yA.y * w; o.z = yB.x * w; o.w = yB.y * w;
        *(float4*)(d_ys + (size_t)(r0 + ty * 4 + j) * H_DIM + h0 + tx * 4) = o;
    }
}

// out[t] = ys[row(t,0)] + ys[row(t,1)]  (weights already applied; deterministic)
__global__ void k_combine(float* __restrict__ out) {
    int t = blockIdx.x;
    int ra = d_row_of[2 * t];
    int rb = d_row_of[2 * t + 1];
    const float4* pa = (const float4*)(d_ys + (size_t)ra * H_DIM);
    const float4* pb = (const float4*)(d_ys + (size_t)rb * H_DIM);
    float4* po = (float4*)(out + (size_t)t * H_DIM);
    for (int i = threadIdx.x; i < H_DIM / 4; i += blockDim.x) {
        float4 a = pa[i], b = pb[i];
        float4 o; o.x = a.x + b.x; o.y = a.y + b.y; o.z = a.z + b.z; o.w = a.w + b.w;
        po[i] = o;
    }
}

// ---------------------------------------------------------------------------
extern "C" void kernel_launch(void* const* d_in, const int* in_sizes, int n_in,
                              void* d_out, int out_size) {
    const float* x  = (const float*)d_in[0];   // hidden_states [1,2048,2048]
    const float* gw = (const float*)d_in[1];   // gate_w [8,2048]
    const float* wg = (const float*)d_in[2];   // w_gate [8,5632,2048]
    const float* wu = (const float*)d_in[3];   // w_up   [8,5632,2048]
    const float* wd = (const float*)d_in[4];   // w_down [8,2048,5632]
    float* out = (float*)d_out;                // [1,2048,2048]

    k_init<<<1, 32>>>();
    k_router<<<T_TOK / 8, 256>>>(x, gw);
    k_offsets<<<1, 1>>>();
    k_gather<<<T_TOK * 2, 256>>>(x);

    dim3 g1(I_DIM / 64, MAXT);
    k_gemm1<<<g1, 256>>>(wg, wu);

    dim3 g2(H_DIM / 64, MAXT);
    k_gemm2<<<g2, 256>>>(wd);

    k_combine<<<T_TOK, 256>>>(out);
}

// round 4
// speedup vs baseline: 1.9868x; 1.9833x over previous
#include <cuda_runtime.h>
#include <cuda_bf16.h>
#include <cstdint>

#define T_TOK 2048
#define H_DIM 2048
#define I_DIM 5632
#define N_EXP 8
#define MAXT  40
#define RMAX  (MAXT * 128)
#define NCH1  (H_DIM / 32)   /* 64  */
#define NCH2  (I_DIM / 32)   /* 176 */

// ---------------- scratch (static device globals; allocation-free) ----------
__device__ float d_Xg [RMAX * H_DIM];
__device__ float d_act[(size_t)RMAX * I_DIM];
__device__ float d_ys [RMAX * H_DIM];
__device__ int   d_topi[T_TOK * 2];
__device__ float d_topw[T_TOK * 2];
__device__ int   d_cnt [N_EXP];
__device__ int   d_fill[N_EXP];
__device__ int   d_off [N_EXP];
__device__ int   d_tile_expert[MAXT];
__device__ int   d_ntiles;
__device__ float d_row_w[RMAX];
__device__ int   d_row_of[T_TOK * 2];

// ---------------- helpers ----------------------------------------------------
__device__ __forceinline__ void split2(float a, float b, uint32_t& h, uint32_t& l) {
    __nv_bfloat16 ah = __float2bfloat16_rn(a), bh = __float2bfloat16_rn(b);
    float ar = a - __bfloat162float(ah);
    float br = b - __bfloat162float(bh);
    __nv_bfloat16 al = __float2bfloat16_rn(ar), bl = __float2bfloat16_rn(br);
    h = ((uint32_t)__bfloat16_as_ushort(bh) << 16) | __bfloat16_as_ushort(ah);
    l = ((uint32_t)__bfloat16_as_ushort(bl) << 16) | __bfloat16_as_ushort(al);
}

__device__ __forceinline__ void split8(const float4& x, const float4& y, uint4& h, uint4& l) {
    uint32_t h0, l0, h1, l1, h2, l2, h3, l3;
    split2(x.x, x.y, h0, l0); split2(x.z, x.w, h1, l1);
    split2(y.x, y.y, h2, l2); split2(y.z, y.w, h3, l3);
    h = make_uint4(h0, h1, h2, h3);
    l = make_uint4(l0, l1, l2, l3);
}

__device__ __forceinline__ void mma16816(float* c,
    uint32_t a0, uint32_t a1, uint32_t a2, uint32_t a3, uint32_t b0, uint32_t b1) {
    asm("mma.sync.aligned.m16n8k16.row.col.f32.bf16.bf16.f32 "
        "{%0,%1,%2,%3}, {%4,%5,%6,%7}, {%8,%9}, {%0,%1,%2,%3};"
        : "+f"(c[0]), "+f"(c[1]), "+f"(c[2]), "+f"(c[3])
        : "r"(a0), "r"(a1), "r"(a2), "r"(a3), "r"(b0), "r"(b1));
}

// 16B-granule XOR swizzle: rows at 64B stride, 8 consecutive rows hit 8 distinct
// 16B bank-groups for ldmatrix-style per-lane LDS.32 fragment loads.
__device__ __forceinline__ uint32_t swz(int r) { return ((uint32_t)(r >> 1) & 3u) << 4; }

__device__ __forceinline__ float silu(float g) { return g / (1.f + __expf(-g)); }

// ---------------- routing ----------------------------------------------------
__global__ void k_init() {
    int i = threadIdx.x;
    if (i < N_EXP) { d_cnt[i] = 0; d_fill[i] = 0; }
}

__global__ void k_router(const float* __restrict__ x, const float* __restrict__ gw) {
    int warp = threadIdx.x >> 5, lane = threadIdx.x & 31;
    int t = blockIdx.x * 8 + warp;
    const float* xr = x + (size_t)t * H_DIM;
    float acc[N_EXP];
#pragma unroll
    for (int e = 0; e < N_EXP; e++) acc[e] = 0.f;
    for (int h = lane; h < H_DIM; h += 32) {
        float xv = xr[h];
#pragma unroll
        for (int e = 0; e < N_EXP; e++) acc[e] += xv * gw[e * H_DIM + h];
    }
#pragma unroll
    for (int e = 0; e < N_EXP; e++)
#pragma unroll
        for (int o = 16; o > 0; o >>= 1) acc[e] += __shfl_xor_sync(0xffffffffu, acc[e], o);

    if (lane == 0) {
        float mx = acc[0];
#pragma unroll
        for (int e = 1; e < N_EXP; e++) mx = fmaxf(mx, acc[e]);
        float p[N_EXP], s = 0.f;
#pragma unroll
        for (int e = 0; e < N_EXP; e++) { p[e] = __expf(acc[e] - mx); s += p[e]; }
        float inv = 1.f / s;
#pragma unroll
        for (int e = 0; e < N_EXP; e++) p[e] *= inv;
        int i0 = 0;
#pragma unroll
        for (int e = 1; e < N_EXP; e++) if (p[e] > p[i0]) i0 = e;
        int i1 = (i0 == 0) ? 1 : 0;
#pragma unroll
        for (int e = 0; e < N_EXP; e++) if (e != i0 && p[e] > p[i1]) i1 = e;
        float sw = p[i0] + p[i1];
        d_topi[2 * t] = i0;     d_topw[2 * t]     = p[i0] / sw;
        d_topi[2 * t + 1] = i1; d_topw[2 * t + 1] = p[i1] / sw;
        atomicAdd(&d_cnt[i0], 1);
        atomicAdd(&d_cnt[i1], 1);
    }
}

__global__ void k_offsets() {
    if (threadIdx.x == 0) {
        int acc = 0;
        for (int e = 0; e < N_EXP; e++) {
            d_off[e] = acc;
            int nt = (d_cnt[e] + 127) >> 7;
            int tb = acc >> 7;
            for (int j = 0; j < nt; j++) d_tile_expert[tb + j] = e;
            acc += nt << 7;
        }
        d_ntiles = acc >> 7;
    }
}

__global__ void k_gather(const float* __restrict__ x) {
    int idx = blockIdx.x;
    int t = idx >> 1;
    __shared__ int rs;
    if (threadIdx.x == 0) {
        int e = d_topi[idx];
        int pos = atomicAdd(&d_fill[e], 1);
        int row = d_off[e] + pos;
        d_row_w[row] = d_topw[idx];
        d_row_of[idx] = row;
        rs = row;
    }
    __syncthreads();
    int row = rs;
    const float4* src = (const float4*)(x + (size_t)t * H_DIM);
    float4* dst = (float4*)(d_Xg + (size_t)row * H_DIM);
    for (int i = threadIdx.x; i < H_DIM / 4; i += blockDim.x) dst[i] = src[i];
}

// ---------------- GEMM1: act = silu(Xg·Wg^T) * (Xg·Wu^T) --------------------
// CTA tile 128(rows) x 64(I). BK=32. 8 warps as 4m x 2n, warp tile 32x32.
#define G1_AH 0
#define G1_AL 8192
#define G1_GH 16384
#define G1_GL 20480
#define G1_UH 24576
#define G1_UL 28672
#define G1_STG 32768
#define G1_SMEM (2 * G1_STG)

__global__ void __launch_bounds__(256, 1)
k_gemm1(const float* __restrict__ wg, const float* __restrict__ wu) {
    const int mtile = blockIdx.y;
    if (mtile >= d_ntiles) return;
    const int e  = d_tile_expert[mtile];
    const int r0 = mtile * 128;
    const int i0 = blockIdx.x * 64;

    extern __shared__ char sm[];
    const int tid = threadIdx.x, lane = tid & 31, wid = tid >> 5;
    const int wm = (wid & 3) * 32;     // warp m base
    const int wn = (wid >> 2) * 32;    // warp n base
    const int lrow = tid >> 1, lhalf = tid & 1;
    const int bsel = tid >> 7, brow = (tid & 127) >> 1;

    const float4* gA = (const float4*)(d_Xg + (size_t)(r0 + lrow) * H_DIM + lhalf * 16);
    const float4* gB = (const float4*)((bsel ? wu : wg) +
                        ((size_t)e * I_DIM + i0 + brow) * H_DIM + lhalf * 16);

    float accg[2][4][4], accu[2][4][4];
#pragma unroll
    for (int m = 0; m < 2; m++)
#pragma unroll
        for (int n = 0; n < 4; n++)
#pragma unroll
            for (int q = 0; q < 4; q++) { accg[m][n][q] = 0.f; accu[m][n][q] = 0.f; }

    float4 vA[4], vB[4];
#pragma unroll
    for (int q = 0; q < 4; q++) { vA[q] = gA[q]; vB[q] = gB[q]; }

    const uint32_t aro = lrow * 64, asx = swz(lrow), akb = lhalf * 32;
    const uint32_t bro = brow * 64, bsx = swz(brow);
    const int boh = bsel ? G1_UH : G1_GH;
    const int bol = bsel ? G1_UL : G1_GL;

#define G1_STORE(st) do {                                                   \
    char* s_ = sm + (st) * G1_STG;                                          \
    uint4 h_, l_;                                                           \
    split8(vA[0], vA[1], h_, l_);                                           \
    *(uint4*)(s_ + G1_AH + aro + (akb ^ asx)) = h_;                         \
    *(uint4*)(s_ + G1_AL + aro + (akb ^ asx)) = l_;                         \
    split8(vA[2], vA[3], h_, l_);                                           \
    *(uint4*)(s_ + G1_AH + aro + ((akb + 16) ^ asx)) = h_;                  \
    *(uint4*)(s_ + G1_AL + aro + ((akb + 16) ^ asx)) = l_;                  \
    split8(vB[0], vB[1], h_, l_);                                           \
    *(uint4*)(s_ + boh + bro + (akb ^ bsx)) = h_;                           \
    *(uint4*)(s_ + bol + bro + (akb ^ bsx)) = l_;                           \
    split8(vB[2], vB[3], h_, l_);                                           \
    *(uint4*)(s_ + boh + bro + ((akb + 16) ^ bsx)) = h_;                    \
    *(uint4*)(s_ + bol + bro + ((akb + 16) ^ bsx)) = l_;                    \
} while (0)

    G1_STORE(0);
    __syncthreads();

    for (int c = 0; c < NCH1; c++) {
        const int b = c & 1;
        if (c + 1 < NCH1) {
#pragma unroll
            for (int q = 0; q < 4; q++) {
                vA[q] = gA[(c + 1) * 8 + q];
                vB[q] = gB[(c + 1) * 8 + q];
            }
        }
        const char* s = sm + b * G1_STG;
#pragma unroll
        for (int ks = 0; ks < 2; ks++) {
            const uint32_t kb0 = ks * 32 + (lane & 3) * 4;
            uint32_t bgh[4][2], bgl[4][2], buh[4][2], bul[4][2];
#pragma unroll
            for (int nt = 0; nt < 4; nt++) {
                int n = wn + nt * 8 + (lane >> 2);
                uint32_t ro = n * 64, sx = swz(n);
                uint32_t o0 = ro + (kb0 ^ sx), o1 = ro + ((kb0 + 16) ^ sx);
                bgh[nt][0] = *(const uint32_t*)(s + G1_GH + o0);
                bgh[nt][1] = *(const uint32_t*)(s + G1_GH + o1);
                bgl[nt][0] = *(const uint32_t*)(s + G1_GL + o0);
                bgl[nt][1] = *(const uint32_t*)(s + G1_GL + o1);
                buh[nt][0] = *(const uint32_t*)(s + G1_UH + o0);
                buh[nt][1] = *(const uint32_t*)(s + G1_UH + o1);
                bul[nt][0] = *(const uint32_t*)(s + G1_UL + o0);
                bul[nt][1] = *(const uint32_t*)(s + G1_UL + o1);
            }
#pragma unroll
            for (int m = 0; m < 2; m++) {
                int r  = wm + m * 16 + (lane >> 2);
                int r8 = r + 8;
                uint32_t o0  = r  * 64 + (kb0 ^ swz(r));
                uint32_t o0b = r  * 64 + ((kb0 + 16) ^ swz(r));
                uint32_t o1  = r8 * 64 + (kb0 ^ swz(r8));
                uint32_t o1b = r8 * 64 + ((kb0 + 16) ^ swz(r8));
                uint32_t ah0 = *(const uint32_t*)(s + G1_AH + o0);
                uint32_t ah1 = *(const uint32_t*)(s + G1_AH + o1);
                uint32_t ah2 = *(const uint32_t*)(s + G1_AH + o0b);
                uint32_t ah3 = *(const uint32_t*)(s + G1_AH + o1b);
                uint32_t al0 = *(const uint32_t*)(s + G1_AL + o0);
                uint32_t al1 = *(const uint32_t*)(s + G1_AL + o1);
                uint32_t al2 = *(const uint32_t*)(s + G1_AL + o0b);
                uint32_t al3 = *(const uint32_t*)(s + G1_AL + o1b);
#pragma unroll
                for (int nt = 0; nt < 4; nt++) {
                    mma16816(accg[m][nt], ah0, ah1, ah2, ah3, bgh[nt][0], bgh[nt][1]);
                    mma16816(accg[m][nt], al0, al1, al2, al3, bgh[nt][0], bgh[nt][1]);
                    mma16816(accg[m][nt], ah0, ah1, ah2, ah3, bgl[nt][0], bgl[nt][1]);
                    mma16816(accu[m][nt], ah0, ah1, ah2, ah3, buh[nt][0], buh[nt][1]);
                    mma16816(accu[m][nt], al0, al1, al2, al3, buh[nt][0], buh[nt][1]);
                    mma16816(accu[m][nt], ah0, ah1, ah2, ah3, bul[nt][0], bul[nt][1]);
                }
            }
        }
        __syncthreads();
        if (c + 1 < NCH1) {
            G1_STORE(1 - b);
            __syncthreads();
        }
    }

#pragma unroll
    for (int m = 0; m < 2; m++)
#pragma unroll
        for (int nt = 0; nt < 4; nt++) {
            int row = r0 + wm + m * 16 + (lane >> 2);
            int col = i0 + wn + nt * 8 + (lane & 3) * 2;
            float2 o0, o1;
            o0.x = silu(accg[m][nt][0]) * accu[m][nt][0];
            o0.y = silu(accg[m][nt][1]) * accu[m][nt][1];
            o1.x = silu(accg[m][nt][2]) * accu[m][nt][2];
            o1.y = silu(accg[m][nt][3]) * accu[m][nt][3];
            *(float2*)(d_act + (size_t)row * I_DIM + col) = o0;
            *(float2*)(d_act + (size_t)(row + 8) * I_DIM + col) = o1;
        }
}

// ---------------- GEMM2: ys = row_w * (act·Wd^T) ----------------------------
// CTA tile 128 x 128. BK=32. 8 warps as 2m x 4n, warp tile 64x32.
#define G2_AH 0
#define G2_AL 8192
#define G2_BH 16384
#define G2_BL 24576
#define G2_STG 32768
#define G2_SMEM (2 * G2_STG)

__global__ void __launch_bounds__(256, 1)
k_gemm2(const float* __restrict__ wd) {
    const int mtile = blockIdx.y;
    if (mtile >= d_ntiles) return;
    const int e  = d_tile_expert[mtile];
    const int r0 = mtile * 128;
    const int h0 = blockIdx.x * 128;

    extern __shared__ char sm[];
    const int tid = threadIdx.x, lane = tid & 31, wid = tid >> 5;
    const int wm = (wid & 1) * 64;     // warp m base (4 m16 tiles)
    const int wn = (wid >> 1) * 32;    // warp n base (4 n8 tiles)
    const int lrow = tid >> 1, lhalf = tid & 1;

    const float4* gA = (const float4*)(d_act + (size_t)(r0 + lrow) * I_DIM + lhalf * 16);
    const float4* gB = (const float4*)(wd + ((size_t)e * H_DIM + h0 + lrow) * I_DIM + lhalf * 16);

    float acc[4][4][4];
#pragma unroll
    for (int m = 0; m < 4; m++)
#pragma unroll
        for (int n = 0; n < 4; n++)
#pragma unroll
            for (int q = 0; q < 4; q++) acc[m][n][q] = 0.f;

    float4 vA[4], vB[4];
#pragma unroll
    for (int q = 0; q < 4; q++) { vA[q] = gA[q]; vB[q] = gB[q]; }

    const uint32_t ro = lrow * 64, sx = swz(lrow), kb = lhalf * 32;

#define G2_STORE(st) do {                                                   \
    char* s_ = sm + (st) * G2_STG;                                          \
    uint4 h_, l_;                                                           \
    split8(vA[0], vA[1], h_, l_);                                           \
    *(uint4*)(s_ + G2_AH + ro + (kb ^ sx)) = h_;                            \
    *(uint4*)(s_ + G2_AL + ro + (kb ^ sx)) = l_;                            \
    split8(vA[2], vA[3], h_, l_);                                           \
    *(uint4*)(s_ + G2_AH + ro + ((kb + 16) ^ sx)) = h_;                     \
    *(uint4*)(s_ + G2_AL + ro + ((kb + 16) ^ sx)) = l_;                     \
    split8(vB[0], vB[1], h_, l_);                                           \
    *(uint4*)(s_ + G2_BH + ro + (kb ^ sx)) = h_;                            \
    *(uint4*)(s_ + G2_BL + ro + (kb ^ sx)) = l_;                            \
    split8(vB[2], vB[3], h_, l_);                                           \
    *(uint4*)(s_ + G2_BH + ro + ((kb + 16) ^ sx)) = h_;                     \
    *(uint4*)(s_ + G2_BL + ro + ((kb + 16) ^ sx)) = l_;                     \
} while (0)

    G2_STORE(0);
    __syncthreads();

    for (int c = 0; c < NCH2; c++) {
        const int b = c & 1;
        if (c + 1 < NCH2) {
#pragma unroll
            for (int q = 0; q < 4; q++) {
                vA[q] = gA[(c + 1) * 8 + q];
                vB[q] = gB[(c + 1) * 8 + q];
            }
        }
        const char* s = sm + b * G2_STG;
#pragma unroll
        for (int ks = 0; ks < 2; ks++) {
            const uint32_t kb0 = ks * 32 + (lane & 3) * 4;
            uint32_t bh[4][2], bl[4][2];
#pragma unroll
            for (int nt = 0; nt < 4; nt++) {
                int n = wn + nt * 8 + (lane >> 2);
                uint32_t nro = n * 64, nsx = swz(n);
                uint32_t o0 = nro + (kb0 ^ nsx), o1 = nro + ((kb0 + 16) ^ nsx);
                bh[nt][0] = *(const uint32_t*)(s + G2_BH + o0);
                bh[nt][1] = *(const uint32_t*)(s + G2_BH + o1);
                bl[nt][0] = *(const uint32_t*)(s + G2_BL + o0);
                bl[nt][1] = *(const uint32_t*)(s + G2_BL + o1);
            }
#pragma unroll
            for (int m = 0; m < 4; m++) {
                int r  = wm + m * 16 + (lane >> 2);
                int r8 = r + 8;
                uint32_t o0  = r  * 64 + (kb0 ^ swz(r));
                uint32_t o0b = r  * 64 + ((kb0 + 16) ^ swz(r));
                uint32_t o1  = r8 * 64 + (kb0 ^ swz(r8));
                uint32_t o1b = r8 * 64 + ((kb0 + 16) ^ swz(r8));
                uint32_t ah0 = *(const uint32_t*)(s + G2_AH + o0);
                uint32_t ah1 = *(const uint32_t*)(s + G2_AH + o1);
                uint32_t ah2 = *(const uint32_t*)(s + G2_AH + o0b);
                uint32_t ah3 = *(const uint32_t*)(s + G2_AH + o1b);
                uint32_t al0 = *(const uint32_t*)(s + G2_AL + o0);
                uint32_t al1 = *(const uint32_t*)(s + G2_AL + o1);
                uint32_t al2 = *(const uint32_t*)(s + G2_AL + o0b);
                uint32_t al3 = *(const uint32_t*)(s + G2_AL + o1b);
#pragma unroll
                for (int nt = 0; nt < 4; nt++) {
                    mma16816(acc[m][nt], ah0, ah1, ah2, ah3, bh[nt][0], bh[nt][1]);
                    mma16816(acc[m][nt], al0, al1, al2, al3, bh[nt][0], bh[nt][1]);
                    mma16816(acc[m][nt], ah0, ah1, ah2, ah3, bl[nt][0], bl[nt][1]);
                }
            }
        }
        __syncthreads();
        if (c + 1 < NCH2) {
            G2_STORE(1 - b);
            __syncthreads();
        }
    }

#pragma unroll
    for (int m = 0; m < 4; m++) {
        int row = r0 + wm + m * 16 + (lane >> 2);
        float w0 = d_row_w[row];
        float w1 = d_row_w[row + 8];
#pragma unroll
        for (int nt = 0; nt < 4; nt++) {
            int col = h0 + wn + nt * 8 + (lane & 3) * 2;
            float2 o0, o1;
            o0.x = acc[m][nt][0] * w0;
            o0.y = acc[m][nt][1] * w0;
            o1.x = acc[m][nt][2] * w1;
            o1.y = acc[m][nt][3] * w1;
            *(float2*)(d_ys + (size_t)row * H_DIM + col) = o0;
            *(float2*)(d_ys + (size_t)(row + 8) * H_DIM + col) = o1;
        }
    }
}

// ---------------- combine ----------------------------------------------------
__global__ void k_combine(float* __restrict__ out) {
    int t = blockIdx.x;
    int ra = d_row_of[2 * t];
    int rb = d_row_of[2 * t + 1];
    const float4* pa = (const float4*)(d_ys + (size_t)ra * H_DIM);
    const float4* pb = (const float4*)(d_ys + (size_t)rb * H_DIM);
    float4* po = (float4*)(out + (size_t)t * H_DIM);
    for (int i = threadIdx.x; i < H_DIM / 4; i += blockDim.x) {
        float4 a = pa[i], b = pb[i];
        float4 o;
        o.x = a.x + b.x; o.y = a.y + b.y; o.z = a.z + b.z; o.w = a.w + b.w;
        po[i] = o;
    }
}

// ---------------- launch -----------------------------------------------------
extern "C" void kernel_launch(void* const* d_in, const int* in_sizes, int n_in,
                              void* d_out, int out_size) {
    const float* x  = (const float*)d_in[0];
    const float* gw = (const float*)d_in[1];
    const float* wg = (const float*)d_in[2];
    const float* wu = (const float*)d_in[3];
    const float* wd = (const float*)d_in[4];
    float* out = (float*)d_out;

    cudaFuncSetAttribute(k_gemm1, cudaFuncAttributeMaxDynamicSharedMemorySize, G1_SMEM);
    cudaFuncSetAttribute(k_gemm2, cudaFuncAttributeMaxDynamicSharedMemorySize, G2_SMEM);

    k_init<<<1, 32>>>();
    k_router<<<T_TOK / 8, 256>>>(x, gw);
    k_offsets<<<1, 1>>>();
    k_gather<<<T_TOK * 2, 256>>>(x);

    dim3 g1(I_DIM / 64, MAXT);
    k_gemm1<<<g1, 256, G1_SMEM>>>(wg, wu);

    dim3 g2(H_DIM / 128, MAXT);
    k_gemm2<<<g2, 256, G2_SMEM>>>(wd);

    k_combine<<<T_TOK, 256>>>(out);
}

// round 5
// speedup vs baseline: 2.6196x; 1.3185x over previous
#include <cuda_runtime.h>
#include <cuda_bf16.h>
#include <cstdint>

#define T_TOK 2048
#define H_DIM 2048
#define I_DIM 5632
#define N_EXP 8
#define MAXT  40
#define RMAX  (MAXT * 128)
#define NCH1  (H_DIM / 32)   /* 64  */
#define NCH2  (I_DIM / 32)   /* 176 */

// ---------------- scratch ----------------------------------------------------
__device__ float d_Xg [RMAX * H_DIM];
__device__ float d_act[(size_t)RMAX * I_DIM];
__device__ float d_ys [RMAX * H_DIM];
__device__ int   d_topi[T_TOK * 2];
__device__ float d_topw[T_TOK * 2];
__device__ int   d_cnt [N_EXP];
__device__ int   d_fill[N_EXP];
__device__ int   d_off [N_EXP];
__device__ int   d_tile_expert[MAXT];
__device__ int   d_ntiles;
__device__ float d_row_w[RMAX];
__device__ int   d_row_of[T_TOK * 2];

// ---------------- helpers ----------------------------------------------------
__device__ __forceinline__ uint32_t smem_u32(const void* p) {
    uint32_t a;
    asm("{ .reg .u64 t; cvta.to.shared.u64 t, %1; cvt.u32.u64 %0, t; }" : "=r"(a) : "l"(p));
    return a;
}

// fast split: 2 fp32 -> packed bf16x2 hi + lo (6 SASS ops)
__device__ __forceinline__ void split2(float a, float b, uint32_t& h, uint32_t& l) {
    asm("cvt.rn.bf16x2.f32 %0, %1, %2;" : "=r"(h) : "f"(b), "f"(a));
    float af = __uint_as_float(h << 16);
    float bf = __uint_as_float(h & 0xffff0000u);
    asm("cvt.rn.bf16x2.f32 %0, %1, %2;" : "=r"(l) : "f"(b - bf), "f"(a - af));
}

__device__ __forceinline__ void split8(const float4& x, const float4& y, uint4& h, uint4& l) {
    split2(x.x, x.y, h.x, l.x); split2(x.z, x.w, h.y, l.y);
    split2(y.x, y.y, h.z, l.z); split2(y.z, y.w, h.w, l.w);
}

__device__ __forceinline__ void mma16816(float* c,
    uint32_t a0, uint32_t a1, uint32_t a2, uint32_t a3, uint32_t b0, uint32_t b1) {
    asm("mma.sync.aligned.m16n8k16.row.col.f32.bf16.bf16.f32 "
        "{%0,%1,%2,%3}, {%4,%5,%6,%7}, {%8,%9}, {%0,%1,%2,%3};"
        : "+f"(c[0]), "+f"(c[1]), "+f"(c[2]), "+f"(c[3])
        : "r"(a0), "r"(a1), "r"(a2), "r"(a3), "r"(b0), "r"(b1));
}

#define LDSM4(r, a) \
    asm volatile("ldmatrix.sync.aligned.m8n8.x4.shared.b16 {%0,%1,%2,%3}, [%4];" \
        : "=r"((r)[0]), "=r"((r)[1]), "=r"((r)[2]), "=r"((r)[3]) : "r"(a))

// 16B-granule XOR swizzle on 64B rows
__device__ __forceinline__ uint32_t swz(int r) { return ((uint32_t)(r >> 1) & 3u) << 4; }

__device__ __forceinline__ float silu(float g) { return g / (1.f + __expf(-g)); }

// ---------------- routing ----------------------------------------------------
__global__ void k_init() {
    int i = threadIdx.x;
    if (i < N_EXP) { d_cnt[i] = 0; d_fill[i] = 0; }
}

__global__ void k_router(const float* __restrict__ x, const float* __restrict__ gw) {
    int warp = threadIdx.x >> 5, lane = threadIdx.x & 31;
    int t = blockIdx.x * 8 + warp;
    const float* xr = x + (size_t)t * H_DIM;
    float acc[N_EXP];
#pragma unroll
    for (int e = 0; e < N_EXP; e++) acc[e] = 0.f;
    for (int h = lane; h < H_DIM; h += 32) {
        float xv = xr[h];
#pragma unroll
        for (int e = 0; e < N_EXP; e++) acc[e] += xv * gw[e * H_DIM + h];
    }
#pragma unroll
    for (int e = 0; e < N_EXP; e++)
#pragma unroll
        for (int o = 16; o > 0; o >>= 1) acc[e] += __shfl_xor_sync(0xffffffffu, acc[e], o);

    if (lane == 0) {
        float mx = acc[0];
#pragma unroll
        for (int e = 1; e < N_EXP; e++) mx = fmaxf(mx, acc[e]);
        float p[N_EXP], s = 0.f;
#pragma unroll
        for (int e = 0; e < N_EXP; e++) { p[e] = __expf(acc[e] - mx); s += p[e]; }
        float inv = 1.f / s;
#pragma unroll
        for (int e = 0; e < N_EXP; e++) p[e] *= inv;
        int i0 = 0;
#pragma unroll
        for (int e = 1; e < N_EXP; e++) if (p[e] > p[i0]) i0 = e;
        int i1 = (i0 == 0) ? 1 : 0;
#pragma unroll
        for (int e = 0; e < N_EXP; e++) if (e != i0 && p[e] > p[i1]) i1 = e;
        float sw = p[i0] + p[i1];
        d_topi[2 * t] = i0;     d_topw[2 * t]     = p[i0] / sw;
        d_topi[2 * t + 1] = i1; d_topw[2 * t + 1] = p[i1] / sw;
        atomicAdd(&d_cnt[i0], 1);
        atomicAdd(&d_cnt[i1], 1);
    }
}

__global__ void k_offsets() {
    if (threadIdx.x == 0) {
        int acc = 0;
        for (int e = 0; e < N_EXP; e++) {
            d_off[e] = acc;
            int nt = (d_cnt[e] + 127) >> 7;
            int tb = acc >> 7;
            for (int j = 0; j < nt; j++) d_tile_expert[tb + j] = e;
            acc += nt << 7;
        }
        d_ntiles = acc >> 7;
    }
}

__global__ void k_gather(const float* __restrict__ x) {
    int idx = blockIdx.x;
    int t = idx >> 1;
    __shared__ int rs;
    if (threadIdx.x == 0) {
        int e = d_topi[idx];
        int pos = atomicAdd(&d_fill[e], 1);
        int row = d_off[e] + pos;
        d_row_w[row] = d_topw[idx];
        d_row_of[idx] = row;
        rs = row;
    }
    __syncthreads();
    int row = rs;
    const float4* src = (const float4*)(x + (size_t)t * H_DIM);
    float4* dst = (float4*)(d_Xg + (size_t)row * H_DIM);
    for (int i = threadIdx.x; i < H_DIM / 4; i += blockDim.x) dst[i] = src[i];
}

// ---------------- GEMM1: act = silu(Xg·Wg^T) * (Xg·Wu^T) --------------------
// CTA tile 128(m) x 64(I).  warps 4m x 2n, warp tile 32x32 (gate and up).
#define G1_AH 0
#define G1_AL 8192
#define G1_GH 16384
#define G1_GL 20480
#define G1_UH 24576
#define G1_UL 28672
#define G1_STG 32768
#define G1_SMEM (2 * G1_STG)

__global__ void __launch_bounds__(256, 1)
k_gemm1(const float* __restrict__ wg, const float* __restrict__ wu) {
    const int mtile = blockIdx.x;              // fastest: weight-tile L2 reuse
    if (mtile >= d_ntiles) return;
    const int e  = d_tile_expert[mtile];
    const int r0 = mtile * 128;
    const int i0 = blockIdx.y * 64;

    extern __shared__ char sm[];
    const uint32_t sbase = smem_u32(sm);
    const int tid = threadIdx.x, lane = tid & 31, wid = tid >> 5;
    const int wm = (wid & 3) * 32;
    const int wn = (wid >> 2) * 32;

    // staging mapping
    const int arow = tid >> 1, ahalf = tid & 1;
    const int bsel = tid >> 7, brow = (tid & 127) >> 1;

    const float4* gA = (const float4*)(d_Xg + (size_t)(r0 + arow) * H_DIM + ahalf * 16);
    const float4* gB = (const float4*)((bsel ? wu : wg) +
                        ((size_t)e * I_DIM + i0 + brow) * H_DIM + ahalf * 16);

    const uint32_t aro = arow * 64, asx = swz(arow), akb = ahalf * 32;
    const uint32_t bro = brow * 64, bsx = swz(brow);
    const int boh = bsel ? G1_UH : G1_GH;
    const int bol = bsel ? G1_UL : G1_GL;

    // ldmatrix lane geometry
    const int lj = lane >> 3, li = lane & 7;
    const int arsel = li + ((lj & 1) << 3);
    const uint32_t akj = (uint32_t)((lj >> 1) << 4);
    const int brsel = li + ((lj >> 1) << 3);
    const uint32_t bkj = (uint32_t)((lj & 1) << 4);

    uint32_t faro[2], fasx[2], fbro[2], fbsx[2];
#pragma unroll
    for (int m = 0; m < 2; m++) {
        int r = wm + m * 16 + arsel;
        faro[m] = r * 64; fasx[m] = swz(r);
    }
#pragma unroll
    for (int p = 0; p < 2; p++) {
        int n = wn + p * 16 + brsel;
        fbro[p] = n * 64; fbsx[p] = swz(n);
    }

    float accg[2][4][4], accu[2][4][4];
#pragma unroll
    for (int m = 0; m < 2; m++)
#pragma unroll
        for (int n = 0; n < 4; n++)
#pragma unroll
            for (int q = 0; q < 4; q++) { accg[m][n][q] = 0.f; accu[m][n][q] = 0.f; }

    float4 vA[4], vB[4];

#define G1_STORE(st) do {                                                   \
    char* s_ = sm + (st) * G1_STG;                                          \
    uint4 h_, l_;                                                           \
    split8(vA[0], vA[1], h_, l_);                                           \
    *(uint4*)(s_ + G1_AH + aro + (akb ^ asx)) = h_;                         \
    *(uint4*)(s_ + G1_AL + aro + (akb ^ asx)) = l_;                         \
    split8(vA[2], vA[3], h_, l_);                                           \
    *(uint4*)(s_ + G1_AH + aro + ((akb + 16) ^ asx)) = h_;                  \
    *(uint4*)(s_ + G1_AL + aro + ((akb + 16) ^ asx)) = l_;                  \
    split8(vB[0], vB[1], h_, l_);                                           \
    *(uint4*)(s_ + boh + bro + (akb ^ bsx)) = h_;                           \
    *(uint4*)(s_ + bol + bro + (akb ^ bsx)) = l_;                           \
    split8(vB[2], vB[3], h_, l_);                                           \
    *(uint4*)(s_ + boh + bro + ((akb + 16) ^ bsx)) = h_;                    \
    *(uint4*)(s_ + bol + bro + ((akb + 16) ^ bsx)) = l_;                    \
} while (0)

    // prologue: chunk0 -> buf0, prefetch chunk1 to regs
#pragma unroll
    for (int q = 0; q < 4; q++) { vA[q] = gA[q]; vB[q] = gB[q]; }
    G1_STORE(0);
#pragma unroll
    for (int q = 0; q < 4; q++) { vA[q] = gA[8 + q]; vB[q] = gB[8 + q]; }
    __syncthreads();

    for (int c = 0; c < NCH1; c++) {
        const int b = c & 1;
        const uint32_t sb32 = sbase + b * G1_STG;
#pragma unroll
        for (int ks = 0; ks < 2; ks++) {
            const uint32_t kb = ks * 32;
            uint32_t ah[2][4], al[2][4];
#pragma unroll
            for (int m = 0; m < 2; m++) {
                uint32_t ad = sb32 + G1_AH + faro[m] + ((kb + akj) ^ fasx[m]);
                LDSM4(ah[m], ad);
                LDSM4(al[m], ad + (G1_AL - G1_AH));
            }
            uint32_t bgh[2][4], bgl[2][4], buh[2][4], bul[2][4];
#pragma unroll
            for (int p = 0; p < 2; p++) {
                uint32_t bd = sb32 + G1_GH + fbro[p] + ((kb + bkj) ^ fbsx[p]);
                LDSM4(bgh[p], bd);
                LDSM4(bgl[p], bd + (G1_GL - G1_GH));
                LDSM4(buh[p], bd + (G1_UH - G1_GH));
                LDSM4(bul[p], bd + (G1_UL - G1_GH));
            }
#pragma unroll
            for (int m = 0; m < 2; m++)
#pragma unroll
                for (int nt = 0; nt < 4; nt++) {
                    const int p = nt >> 1, q = (nt & 1) * 2;
                    mma16816(accg[m][nt], ah[m][0], ah[m][1], ah[m][2], ah[m][3], bgh[p][q], bgh[p][q + 1]);
                    mma16816(accg[m][nt], al[m][0], al[m][1], al[m][2], al[m][3], bgh[p][q], bgh[p][q + 1]);
                    mma16816(accg[m][nt], ah[m][0], ah[m][1], ah[m][2], ah[m][3], bgl[p][q], bgl[p][q + 1]);
                    mma16816(accu[m][nt], ah[m][0], ah[m][1], ah[m][2], ah[m][3], buh[p][q], buh[p][q + 1]);
                    mma16816(accu[m][nt], al[m][0], al[m][1], al[m][2], al[m][3], buh[p][q], buh[p][q + 1]);
                    mma16816(accu[m][nt], ah[m][0], ah[m][1], ah[m][2], ah[m][3], bul[p][q], bul[p][q + 1]);
                }
        }
        if (c + 1 < NCH1) {
            G1_STORE(1 - b);
            __syncthreads();
            if (c + 2 < NCH1) {
#pragma unroll
                for (int q = 0; q < 4; q++) {
                    vA[q] = gA[(c + 2) * 8 + q];
                    vB[q] = gB[(c + 2) * 8 + q];
                }
            }
        }
    }

#pragma unroll
    for (int m = 0; m < 2; m++)
#pragma unroll
        for (int nt = 0; nt < 4; nt++) {
            int row = r0 + wm + m * 16 + (lane >> 2);
            int col = i0 + wn + nt * 8 + (lane & 3) * 2;
            float2 o0, o1;
            o0.x = silu(accg[m][nt][0]) * accu[m][nt][0];
            o0.y = silu(accg[m][nt][1]) * accu[m][nt][1];
            o1.x = silu(accg[m][nt][2]) * accu[m][nt][2];
            o1.y = silu(accg[m][nt][3]) * accu[m][nt][3];
            *(float2*)(d_act + (size_t)row * I_DIM + col) = o0;
            *(float2*)(d_act + (size_t)(row + 8) * I_DIM + col) = o1;
        }
}

// ---------------- GEMM2: ys = row_w * (act·Wd^T) ----------------------------
// CTA tile 128 x 128.  warps 2m x 4n, warp tile 64x32.
#define G2_AH 0
#define G2_AL 8192
#define G2_BH 16384
#define G2_BL 24576
#define G2_STG 32768
#define G2_SMEM (2 * G2_STG)

__global__ void __launch_bounds__(256, 1)
k_gemm2(const float* __restrict__ wd) {
    const int mtile = blockIdx.x;
    if (mtile >= d_ntiles) return;
    const int e  = d_tile_expert[mtile];
    const int r0 = mtile * 128;
    const int h0 = blockIdx.y * 128;

    extern __shared__ char sm[];
    const uint32_t sbase = smem_u32(sm);
    const int tid = threadIdx.x, lane = tid & 31, wid = tid >> 5;
    const int wm = (wid & 1) * 64;
    const int wn = (wid >> 1) * 32;

    const int arow = tid >> 1, ahalf = tid & 1;

    const float4* gA = (const float4*)(d_act + (size_t)(r0 + arow) * I_DIM + ahalf * 16);
    const float4* gB = (const float4*)(wd + ((size_t)e * H_DIM + h0 + arow) * I_DIM + ahalf * 16);

    const uint32_t aro = arow * 64, asx = swz(arow), akb = ahalf * 32;

    const int lj = lane >> 3, li = lane & 7;
    const int arsel = li + ((lj & 1) << 3);
    const uint32_t akj = (uint32_t)((lj >> 1) << 4);
    const int brsel = li + ((lj >> 1) << 3);
    const uint32_t bkj = (uint32_t)((lj & 1) << 4);

    uint32_t faro[4], fasx[4], fbro[2], fbsx[2];
#pragma unroll
    for (int m = 0; m < 4; m++) {
        int r = wm + m * 16 + arsel;
        faro[m] = r * 64; fasx[m] = swz(r);
    }
#pragma unroll
    for (int p = 0; p < 2; p++) {
        int n = wn + p * 16 + brsel;
        fbro[p] = n * 64; fbsx[p] = swz(n);
    }

    float acc[4][4][4];
#pragma unroll
    for (int m = 0; m < 4; m++)
#pragma unroll
        for (int n = 0; n < 4; n++)
#pragma unroll
            for (int q = 0; q < 4; q++) acc[m][n][q] = 0.f;

    float4 vA[4], vB[4];

#define G2_STORE(st) do {                                                   \
    char* s_ = sm + (st) * G2_STG;                                          \
    uint4 h_, l_;                                                           \
    split8(vA[0], vA[1], h_, l_);                                           \
    *(uint4*)(s_ + G2_AH + aro + (akb ^ asx)) = h_;                         \
    *(uint4*)(s_ + G2_AL + aro + (akb ^ asx)) = l_;                         \
    split8(vA[2], vA[3], h_, l_);                                           \
    *(uint4*)(s_ + G2_AH + aro + ((akb + 16) ^ asx)) = h_;                  \
    *(uint4*)(s_ + G2_AL + aro + ((akb + 16) ^ asx)) = l_;                  \
    split8(vB[0], vB[1], h_, l_);                                           \
    *(uint4*)(s_ + G2_BH + aro + (akb ^ asx)) = h_;                         \
    *(uint4*)(s_ + G2_BL + aro + (akb ^ asx)) = l_;                         \
    split8(vB[2], vB[3], h_, l_);                                           \
    *(uint4*)(s_ + G2_BH + aro + ((akb + 16) ^ asx)) = h_;                  \
    *(uint4*)(s_ + G2_BL + aro + ((akb + 16) ^ asx)) = l_;                  \
} while (0)

#pragma unroll
    for (int q = 0; q < 4; q++) { vA[q] = gA[q]; vB[q] = gB[q]; }
    G2_STORE(0);
#pragma unroll
    for (int q = 0; q < 4; q++) { vA[q] = gA[8 + q]; vB[q] = gB[8 + q]; }
    __syncthreads();

    for (int c = 0; c < NCH2; c++) {
        const int b = c & 1;
        const uint32_t sb32 = sbase + b * G2_STG;
#pragma unroll
        for (int ks = 0; ks < 2; ks++) {
            const uint32_t kb = ks * 32;
            uint32_t bh[2][4], bl[2][4];
#pragma unroll
            for (int p = 0; p < 2; p++) {
                uint32_t bd = sb32 + G2_BH + fbro[p] + ((kb + bkj) ^ fbsx[p]);
                LDSM4(bh[p], bd);
                LDSM4(bl[p], bd + (G2_BL - G2_BH));
            }
#pragma unroll
            for (int m = 0; m < 4; m++) {
                uint32_t ah[4], al[4];
                uint32_t ad = sb32 + G2_AH + faro[m] + ((kb + akj) ^ fasx[m]);
                LDSM4(ah, ad);
                LDSM4(al, ad + (G2_AL - G2_AH));
#pragma unroll
                for (int nt = 0; nt < 4; nt++) {
                    const int p = nt >> 1, q = (nt & 1) * 2;
                    mma16816(acc[m][nt], ah[0], ah[1], ah[2], ah[3], bh[p][q], bh[p][q + 1]);
                    mma16816(acc[m][nt], al[0], al[1], al[2], al[3], bh[p][q], bh[p][q + 1]);
                    mma16816(acc[m][nt], ah[0], ah[1], ah[2], ah[3], bl[p][q], bl[p][q + 1]);
                }
            }
        }
        if (c + 1 < NCH2) {
            G2_STORE(1 - b);
            __syncthreads();
            if (c + 2 < NCH2) {
#pragma unroll
                for (int q = 0; q < 4; q++) {
                    vA[q] = gA[(c + 2) * 8 + q];
                    vB[q] = gB[(c + 2) * 8 + q];
                }
            }
        }
    }

#pragma unroll
    for (int m = 0; m < 4; m++) {
        int row = r0 + wm + m * 16 + (lane >> 2);
        float w0 = d_row_w[row];
        float w1 = d_row_w[row + 8];
#pragma unroll
        for (int nt = 0; nt < 4; nt++) {
            int col = h0 + wn + nt * 8 + (lane & 3) * 2;
            float2 o0, o1;
            o0.x = acc[m][nt][0] * w0;
            o0.y = acc[m][nt][1] * w0;
            o1.x = acc[m][nt][2] * w1;
            o1.y = acc[m][nt][3] * w1;
            *(float2*)(d_ys + (size_t)row * H_DIM + col) = o0;
            *(float2*)(d_ys + (size_t)(row + 8) * H_DIM + col) = o1;
        }
    }
}

// ---------------- combine ----------------------------------------------------
__global__ void k_combine(float* __restrict__ out) {
    int t = blockIdx.x;
    int ra = d_row_of[2 * t];
    int rb = d_row_of[2 * t + 1];
    const float4* pa = (const float4*)(d_ys + (size_t)ra * H_DIM);
    const float4* pb = (const float4*)(d_ys + (size_t)rb * H_DIM);
    float4* po = (float4*)(out + (size_t)t * H_DIM);
    for (int i = threadIdx.x; i < H_DIM / 4; i += blockDim.x) {
        float4 a = pa[i], b = pb[i];
        float4 o;
        o.x = a.x + b.x; o.y = a.y + b.y; o.z = a.z + b.z; o.w = a.w + b.w;
        po[i] = o;
    }
}

// ---------------- launch -----------------------------------------------------
extern "C" void kernel_launch(void* const* d_in, const int* in_sizes, int n_in,
                              void* d_out, int out_size) {
    const float* x  = (const float*)d_in[0];
    const float* gw = (const float*)d_in[1];
    const float* wg = (const float*)d_in[2];
    const float* wu = (const float*)d_in[3];
    const float* wd = (const float*)d_in[4];
    float* out = (float*)d_out;

    cudaFuncSetAttribute(k_gemm1, cudaFuncAttributeMaxDynamicSharedMemorySize, G1_SMEM);
    cudaFuncSetAttribute(k_gemm2, cudaFuncAttributeMaxDynamicSharedMemorySize, G2_SMEM);

    k_init<<<1, 32>>>();
    k_router<<<T_TOK / 8, 256>>>(x, gw);
    k_offsets<<<1, 1>>>();
    k_gather<<<T_TOK * 2, 256>>>(x);

    dim3 g1(MAXT, I_DIM / 64);    // mtile fastest -> weight tile shared in L2
    k_gemm1<<<g1, 256, G1_SMEM>>>(wg, wu);

    dim3 g2(MAXT, H_DIM / 128);
    k_gemm2<<<g2, 256, G2_SMEM>>>(wd);

    k_combine<<<T_TOK, 256>>>(out);
}